// round 2
// baseline (speedup 1.0000x reference)
#include <cuda_runtime.h>

// Problem constants: b=8, dim=64, heads=2, H=W=256
#define NPIX 65536
#define NPAIR 32768   // pixels as float2 pairs

typedef unsigned long long u64;

// ---------------- scratch (device globals; allocation-free rule) ----------------
__device__ float g_qkv [100663296];   // [8][192][65536] after 1x1 conv
__device__ float g_qkvd[100663296];   // [8][192][65536] after depthwise 3x3
__device__ float g_sspart[32768];     // [8][128][32] per-yblock sumsq partials
__device__ float g_part[2097152];     // [8][2][128][1024] attn partial sums
__device__ float g_P   [8 * 64 * 64]; // fused (W_proj * blockdiag(M)) per batch

// ---------------- f32x2 helpers -------------------------------------------------
__device__ __forceinline__ u64 pk2(float a, float b) {
    u64 r; asm("mov.b64 %0,{%1,%2};" : "=l"(r) : "f"(a), "f"(b)); return r;
}
__device__ __forceinline__ u64 fma2(u64 a, u64 b, u64 c) {
    u64 d; asm("fma.rn.f32x2 %0,%1,%2,%3;" : "=l"(d) : "l"(a), "l"(b), "l"(c)); return d;
}
__device__ __forceinline__ float lo32(u64 v) { return __uint_as_float((unsigned)v); }
__device__ __forceinline__ float hi32(u64 v) { return __uint_as_float((unsigned)(v >> 32)); }

// ---------------- K1 / K6: pointwise GEMM out[oc][n] = sum_ic w[oc][ic]*in[ic][n]
// Per-batch base pointers. IC = 64. Block: 64 oc (blockIdx.y slab) x 128 pairs.
// 256 thr: 16 oc-groups x 16 pair-groups, tile 4 oc x 8 pairs, f32x2 accum.
// smem (dynamic 96KB): xs u64[64][128], wsA u64[64][32], wsB u64[64][32]
// (w pre-duplicated into u64 pairs; A holds oc%4 in {0,1}, B holds {2,3}).
__global__ __launch_bounds__(256) void pw_gemm_kernel(
    const u64* __restrict__ in2, const float* __restrict__ wgt, u64* __restrict__ out2)
{
    extern __shared__ u64 smd[];
    u64* xs  = smd;            // 8192
    u64* wsA = smd + 8192;     // 2048
    u64* wsB = smd + 10240;    // 2048
    const int ocb = blockIdx.y * 64;
    const int px2 = blockIdx.x * 128;
    const int tid = threadIdx.x;

    const ulonglong2* inb2 = (const ulonglong2*)(in2 + px2);
    #pragma unroll
    for (int i = 0; i < 16; i++) {
        int li = tid + i * 256;            // 0..4095
        int ic = li >> 6, l2 = li & 63;
        ((ulonglong2*)xs)[ic * 64 + l2] = inb2[(long)ic * 16384 + l2];
    }
    #pragma unroll
    for (int i = 0; i < 16; i++) {
        int li = tid + i * 256;            // 0..4095
        int ic = li & 63, r = li >> 6;     // coalesced over ic
        float w = wgt[(ocb + r) * 64 + ic];
        u64 p = pk2(w, w);
        int ocg = r >> 2, t = r & 3;
        if (t < 2) wsA[ic * 32 + ocg * 2 + t]     = p;
        else       wsB[ic * 32 + ocg * 2 + t - 2] = p;
    }
    __syncthreads();

    const int pxg = tid >> 4;      // 16 groups of 8 pairs
    const int ocg = tid & 15;      // 16 groups of 4 oc
    u64 acc[4][8];
    #pragma unroll
    for (int i = 0; i < 4; i++)
        #pragma unroll
        for (int j = 0; j < 8; j++) acc[i][j] = 0ULL;

    const u64* xrow = xs + pxg * 8;
    const u64* wa = wsA + ocg * 2;
    const u64* wb = wsB + ocg * 2;

    #pragma unroll 4
    for (int ic = 0; ic < 64; ic++) {
        ulonglong2 x01 = *(const ulonglong2*)(xrow + ic * 128);
        ulonglong2 x23 = *(const ulonglong2*)(xrow + ic * 128 + 2);
        ulonglong2 x45 = *(const ulonglong2*)(xrow + ic * 128 + 4);
        ulonglong2 x67 = *(const ulonglong2*)(xrow + ic * 128 + 6);
        ulonglong2 wA  = *(const ulonglong2*)(wa + ic * 32);
        ulonglong2 wB  = *(const ulonglong2*)(wb + ic * 32);
        u64 w4[4] = { wA.x, wA.y, wB.x, wB.y };
        u64 x8[8] = { x01.x, x01.y, x23.x, x23.y, x45.x, x45.y, x67.x, x67.y };
        #pragma unroll
        for (int i = 0; i < 4; i++)
            #pragma unroll
            for (int j = 0; j < 8; j++) acc[i][j] = fma2(w4[i], x8[j], acc[i][j]);
    }

    u64* ob = out2 + (long)(ocb + ocg * 4) * NPAIR + px2 + pxg * 8;
    #pragma unroll
    for (int i = 0; i < 4; i++) {
        ulonglong2* dst = (ulonglong2*)(ob + (long)i * NPAIR);
        dst[0] = make_ulonglong2(acc[i][0], acc[i][1]);
        dst[1] = make_ulonglong2(acc[i][2], acc[i][3]);
        dst[2] = make_ulonglong2(acc[i][4], acc[i][5]);
        dst[3] = make_ulonglong2(acc[i][6], acc[i][7]);
    }
}

// ---------------- K2: depthwise 3x3 pad 1 + fused sumsq partials ----------------
__global__ __launch_bounds__(256) void dw_kernel(const float* __restrict__ w_dw, int b)
{
    __shared__ float s[10][258];
    __shared__ float sm8[8];
    const int ch = blockIdx.y, y0 = blockIdx.x * 8;
    const float* in  = g_qkv  + ((long)b * 192 + ch) * NPIX;
    float*       out = g_qkvd + ((long)b * 192 + ch) * NPIX;
    const int tid = threadIdx.x;

    #pragma unroll
    for (int r = 0; r < 10; r++) {
        int y = y0 - 1 + r;
        s[r][tid + 1] = (y >= 0 && y < 256) ? in[y * 256 + tid] : 0.f;
    }
    if (tid < 10) { s[tid][0] = 0.f; s[tid][257] = 0.f; }
    float w[9];
    #pragma unroll
    for (int i = 0; i < 9; i++) w[i] = w_dw[ch * 9 + i];
    __syncthreads();

    float ss = 0.f;
    #pragma unroll
    for (int ry = 0; ry < 8; ry++) {
        float a = 0.f;
        #pragma unroll
        for (int dy = 0; dy < 3; dy++)
            #pragma unroll
            for (int dx = 0; dx < 3; dx++)
                a += w[dy * 3 + dx] * s[ry + dy][tid + dx];
        out[(y0 + ry) * 256 + tid] = a;
        ss += a * a;
    }
    #pragma unroll
    for (int o = 16; o; o >>= 1) ss += __shfl_xor_sync(0xffffffffu, ss, o);
    if ((tid & 31) == 0) sm8[tid >> 5] = ss;
    __syncthreads();
    if (tid == 0 && ch < 128) {
        float t = 0.f;
        #pragma unroll
        for (int i = 0; i < 8; i++) t += sm8[i];
        g_sspart[((long)b * 128 + ch) * 32 + blockIdx.x] = t;
    }
}

// ---------------- K4: attn partials raw[c][d] = sum_n q[c][n]k[d][n] ------------
// Each warp computes the FULL 32x32 for its own n slice (f32x2 over n-pairs).
// Lane layout: cg = lane>>3 (4 groups of 8 c), dg = lane&7 (8 groups of 4 d).
// XOR-4 swizzle on the n index (by row>>3) makes all operand LDS.128 1-phase.
#define QST 132
__global__ __launch_bounds__(256) void attn_kernel(int b)
{
    __shared__ alignas(16) float qs[2 * 32 * QST];   // q tile, then k tile; reused as red
    float* ks = qs + 32 * QST;
    const int cx = blockIdx.x;            // 128 chunks of 512 n
    const int h  = blockIdx.y;
    const float* qb = g_qkvd + ((long)b * 192 +      h * 32) * NPIX;
    const float* kb = g_qkvd + ((long)b * 192 + 64 + h * 32) * NPIX;
    const int tid = threadIdx.x, wid = tid >> 5, lane = tid & 31;
    const int cg = lane >> 3, dg = lane & 7;
    const int swq = cg * 4;
    const int swk = ((dg >> 1) & 3) * 4;

    u64 acc[8][4];
    #pragma unroll
    for (int i = 0; i < 8; i++)
        #pragma unroll
        for (int j = 0; j < 4; j++) acc[i][j] = 0ULL;

    for (int sc = 0; sc < 4; sc++) {
        const int n0 = cx * 512 + sc * 128;
        if (sc) __syncthreads();
        #pragma unroll
        for (int i = 0; i < 4; i++) {
            int li = tid + i * 256;        // 0..1023
            int c = li >> 5, f4 = li & 31;
            int sw = ((c >> 3) & 3) * 4;
            float4 qv = *(const float4*)(qb + (long)c * NPIX + n0 + f4 * 4);
            float4 kv = *(const float4*)(kb + (long)c * NPIX + n0 + f4 * 4);
            *(float4*)(qs + c * QST + ((f4 * 4) ^ sw)) = qv;
            *(float4*)(ks + c * QST + ((f4 * 4) ^ sw)) = kv;
        }
        __syncthreads();
        #pragma unroll
        for (int qd = 0; qd < 4; qd++) {
            const int nn4 = wid * 16 + qd * 4;
            ulonglong2 q4[8], k4[4];
            #pragma unroll
            for (int i = 0; i < 8; i++)
                q4[i] = *(const ulonglong2*)(qs + (cg * 8 + i) * QST + (nn4 ^ swq));
            #pragma unroll
            for (int j = 0; j < 4; j++)
                k4[j] = *(const ulonglong2*)(ks + (dg * 4 + j) * QST + (nn4 ^ swk));
            #pragma unroll
            for (int i = 0; i < 8; i++)
                #pragma unroll
                for (int j = 0; j < 4; j++) {
                    acc[i][j] = fma2(q4[i].x, k4[j].x, acc[i][j]);
                    acc[i][j] = fma2(q4[i].y, k4[j].y, acc[i][j]);
                }
        }
    }

    __syncthreads();
    float* red = qs;   // 8 warps x 32*33 = 8448 floats = exactly 2*32*QST
    #pragma unroll
    for (int i = 0; i < 8; i++)
        #pragma unroll
        for (int j = 0; j < 4; j++) {
            int c = cg * 8 + i, d = dg * 4 + j;
            red[wid * 1056 + c * 33 + d] = lo32(acc[i][j]) + hi32(acc[i][j]);
        }
    __syncthreads();

    // 1024 outputs; each thread reduces 4 across the 8 warps
    const int c0 = (tid * 4) >> 5, d0 = (tid * 4) & 31;
    float o0 = 0.f, o1 = 0.f, o2 = 0.f, o3 = 0.f;
    #pragma unroll
    for (int w = 0; w < 8; w++) {
        const float* rp = red + w * 1056 + c0 * 33 + d0;
        o0 += rp[0]; o1 += rp[1]; o2 += rp[2]; o3 += rp[3];
    }
    float* gp = g_part + (((long)b * 2 + h) * 128 + cx) * 1024 + tid * 4;
    gp[0] = o0; gp[1] = o1; gp[2] = o2; gp[3] = o3;
}

// ---------------- K5: norms + topk-masked softmax x3 + combine + fused P --------
__global__ __launch_bounds__(1024) void soft_kernel(
    int b, const float* __restrict__ temp, const float* __restrict__ a1,
    const float* __restrict__ a2, const float* __restrict__ a3,
    const float* __restrict__ wp)
{
    const int h = blockIdx.x;
    __shared__ float invq[32], invk[32];
    __shared__ float M[32 * 33];
    const int tid = threadIdx.x;

    if (tid < 64) {
        int isk = tid >> 5, cc = tid & 31;
        const float* sp = g_sspart + ((long)b * 128 + isk * 64 + h * 32 + cc) * 32;
        float s = 0.f;
        #pragma unroll
        for (int p = 0; p < 32; p++) s += sp[p];
        float iv = 1.f / fmaxf(sqrtf(s), 1e-12f);
        if (isk) invk[cc] = iv; else invq[cc] = iv;
    }
    __syncthreads();

    const int c = tid >> 5, d = tid & 31;
    const float* pp = g_part + (((long)b * 2 + h) * 128) * 1024 + c * 32 + d;
    float raw = 0.f;
    #pragma unroll 16
    for (int p = 0; p < 128; p++) raw += pp[p * 1024];

    float v = raw * invq[c] * invk[d] * temp[h];

    // rank with torch.topk tie-break (earlier index wins)
    int rank = 0;
    #pragma unroll
    for (int j = 0; j < 32; j++) {
        float vj = __shfl_sync(0xffffffffu, v, j);
        rank += (vj > v) || (vj == v && j < d);
    }
    float m = v;
    #pragma unroll
    for (int o = 16; o; o >>= 1) m = fmaxf(m, __shfl_xor_sync(0xffffffffu, m, o));
    float e  = expf(v - m);
    float e1 = rank < 16 ? e : 0.f;
    float e2 = rank < 21 ? e : 0.f;
    float e3 = rank < 24 ? e : 0.f;
    float s1 = e1, s2 = e2, s3 = e3;
    #pragma unroll
    for (int o = 16; o; o >>= 1) {
        s1 += __shfl_xor_sync(0xffffffffu, s1, o);
        s2 += __shfl_xor_sync(0xffffffffu, s2, o);
        s3 += __shfl_xor_sync(0xffffffffu, s3, o);
    }
    M[c * 33 + d] = e1 * (a1[0] / s1) + e2 * (a2[0] / s2) + e3 * (a3[0] / s3);
    __syncthreads();

    // P[b][oc][h*32+d] = sum_c wp[oc][h*32+c] * M[c][d] (fuses out-einsum + proj)
    const int oc = tid >> 5, dd = tid & 31;
    float p0 = 0.f, p1 = 0.f;
    #pragma unroll
    for (int cc = 0; cc < 32; cc++) {
        float mm = M[cc * 33 + dd];
        p0 += wp[oc * 64 + h * 32 + cc] * mm;
        p1 += wp[(oc + 32) * 64 + h * 32 + cc] * mm;
    }
    g_P[b * 4096 + oc * 64 + h * 32 + dd]        = p0;
    g_P[b * 4096 + (oc + 32) * 64 + h * 32 + dd] = p1;
}

// ---------------- launch --------------------------------------------------------
extern "C" void kernel_launch(void* const* d_in, const int* in_sizes, int n_in,
                              void* d_out, int out_size)
{
    const float* x      = (const float*)d_in[0];
    const float* w_qkv  = (const float*)d_in[1];
    const float* w_dw   = (const float*)d_in[2];
    const float* w_proj = (const float*)d_in[3];
    const float* temp   = (const float*)d_in[4];
    const float* a1     = (const float*)d_in[5];
    const float* a2     = (const float*)d_in[6];
    const float* a3     = (const float*)d_in[7];

    cudaFuncSetAttribute(pw_gemm_kernel,
                         cudaFuncAttributeMaxDynamicSharedMemorySize, 98304);

    void *pqkv, *pqkvd, *pP;
    cudaGetSymbolAddress(&pqkv,  g_qkv);
    cudaGetSymbolAddress(&pqkvd, g_qkvd);
    cudaGetSymbolAddress(&pP,    g_P);

    for (int b = 0; b < 8; b++) {
        // K1: qkv 1x1 conv for batch b (x -> g_qkv[b])
        pw_gemm_kernel<<<dim3(256, 3), 256, 98304>>>(
            (const u64*)x + (long)b * 64 * NPAIR, w_qkv,
            (u64*)pqkv + (long)b * 192 * NPAIR);
        // K2: depthwise 3x3 (+ fused q/k sumsq partials)
        dw_kernel<<<dim3(32, 192), 256>>>(w_dw, b);
        // K4: attn raw dot-product partials
        attn_kernel<<<dim3(128, 2), 256>>>(b);
        // K5: norms + topk softmax x3 + combine + fused P
        soft_kernel<<<2, 1024>>>(b, temp, a1, a2, a3, w_proj);
        // K6: final = P @ V (V = g_qkvd[b] channels 128..191) -> d_out[b]
        pw_gemm_kernel<<<dim3(256, 1), 256, 98304>>>(
            (const u64*)pqkvd + (long)b * 192 * NPAIR + 128L * NPAIR,
            (const float*)pP + b * 4096,
            (u64*)d_out + (long)b * 64 * NPAIR);
    }
}

// round 5
// speedup vs baseline: 1.3861x; 1.3861x over previous
#include <cuda_runtime.h>

// Problem constants: b=8, dim=64, heads=2, H=W=256
#define NPIX 65536
#define NPAIR 32768   // pixels as float2 pairs

typedef unsigned long long u64;

// ---------------- scratch (device globals; allocation-free rule) ----------------
__device__ float g_qkv [100663296];   // [8][192][65536] after 1x1 conv
__device__ float g_qkvd[100663296];   // [8][192][65536] after depthwise 3x3
__device__ float g_sspart[32768];     // [8][128][32] per-yblock sumsq partials
__device__ float g_part[1048576];     // [8][2][64][1024] attn partial sums
__device__ float g_P   [8 * 64 * 64]; // fused (W_proj * blockdiag(M)) per batch

// ---------------- f32x2 helpers -------------------------------------------------
__device__ __forceinline__ u64 pk2(float a, float b) {
    u64 r; asm("mov.b64 %0,{%1,%2};" : "=l"(r) : "f"(a), "f"(b)); return r;
}
__device__ __forceinline__ u64 fma2(u64 a, u64 b, u64 c) {
    u64 d; asm("fma.rn.f32x2 %0,%1,%2,%3;" : "=l"(d) : "l"(a), "l"(b), "l"(c)); return d;
}
__device__ __forceinline__ float lo32(u64 v) { return __uint_as_float((unsigned)v); }
__device__ __forceinline__ float hi32(u64 v) { return __uint_as_float((unsigned)(v >> 32)); }

// ---------------- K1: qkv 1x1 conv, all 192 oc per block ------------------------
// Block: 128 pairs (256 px) x 192 oc, looped as 3 slabs of 64 oc over one x tile.
// 256 thr: 16 pair-groups x 16 oc-groups; thread tile 4 oc x 8 pairs, f32x2 accum.
// smem 112KB: xs u64[64][128] (64KB) + ws float[64][192] transposed (48KB).
__global__ __launch_bounds__(256, 2) void qkv_kernel(
    const u64* __restrict__ in2, const float* __restrict__ wgt, u64* __restrict__ out2)
{
    extern __shared__ u64 smd[];
    u64*   xs = smd;                    // 8192 u64
    float* ws = (float*)(smd + 8192);   // 12288 f32, [ic][192]
    const int b   = blockIdx.z;
    const int px2 = blockIdx.x * 128;
    const int tid = threadIdx.x;

    const ulonglong2* inb2 = (const ulonglong2*)(in2 + (long)b * 64 * NPAIR + px2);
    #pragma unroll
    for (int i = 0; i < 16; i++) {
        int li = tid + i * 256;            // 0..4095
        int ic = li >> 6, l2 = li & 63;
        ((ulonglong2*)xs)[ic * 64 + l2] = inb2[(long)ic * 16384 + l2];
    }
    // transpose weights into smem: ws[ic][oc]; smem writes conflict-free (oc fastest)
    for (int idx = tid; idx < 12288; idx += 256) {
        int ic = idx / 192, oc = idx - ic * 192;
        ws[ic * 192 + oc] = wgt[oc * 64 + ic];   // gmem stride-64: L2-hot (48KB)
    }
    __syncthreads();

    const int pxg = tid >> 4;      // 16 groups of 8 pairs
    const int ocg = tid & 15;      // 16 groups of 4 oc
    const u64* xrow = xs + pxg * 8;

    #pragma unroll 1
    for (int slab = 0; slab < 3; slab++) {
        u64 acc[4][8];
        #pragma unroll
        for (int i = 0; i < 4; i++)
            #pragma unroll
            for (int j = 0; j < 8; j++) acc[i][j] = 0ULL;

        const float* wrow = ws + slab * 64 + ocg * 4;
        #pragma unroll 4
        for (int ic = 0; ic < 64; ic++) {
            float4 wf = *(const float4*)(wrow + ic * 192);
            u64 w4[4] = { pk2(wf.x, wf.x), pk2(wf.y, wf.y),
                          pk2(wf.z, wf.z), pk2(wf.w, wf.w) };
            ulonglong2 x01 = *(const ulonglong2*)(xrow + ic * 128);
            ulonglong2 x23 = *(const ulonglong2*)(xrow + ic * 128 + 2);
            ulonglong2 x45 = *(const ulonglong2*)(xrow + ic * 128 + 4);
            ulonglong2 x67 = *(const ulonglong2*)(xrow + ic * 128 + 6);
            u64 x8[8] = { x01.x, x01.y, x23.x, x23.y, x45.x, x45.y, x67.x, x67.y };
            #pragma unroll
            for (int i = 0; i < 4; i++)
                #pragma unroll
                for (int j = 0; j < 8; j++) acc[i][j] = fma2(w4[i], x8[j], acc[i][j]);
        }

        u64* ob = out2 + (long)b * 192 * NPAIR
                       + (long)(slab * 64 + ocg * 4) * NPAIR + px2 + pxg * 8;
        #pragma unroll
        for (int i = 0; i < 4; i++) {
            ulonglong2* dst = (ulonglong2*)(ob + (long)i * NPAIR);
            dst[0] = make_ulonglong2(acc[i][0], acc[i][1]);
            dst[1] = make_ulonglong2(acc[i][2], acc[i][3]);
            dst[2] = make_ulonglong2(acc[i][4], acc[i][5]);
            dst[3] = make_ulonglong2(acc[i][6], acc[i][7]);
        }
    }
}

// ---------------- K6: final GEMM out[oc][n] = sum_ic P[oc][ic]*v[ic][n] ---------
__global__ __launch_bounds__(256) void pw_gemm_kernel(
    const u64* __restrict__ in2, const float* __restrict__ wgt, u64* __restrict__ out2,
    long in_bs2, long out_bs2, int wgt_bs)
{
    extern __shared__ u64 smd[];
    u64* xs  = smd;            // 8192
    u64* wsA = smd + 8192;     // 2048
    u64* wsB = smd + 10240;    // 2048
    const int b   = blockIdx.z;
    const int px2 = blockIdx.x * 128;
    const int tid = threadIdx.x;

    const ulonglong2* inb2 = (const ulonglong2*)(in2 + (long)b * in_bs2 + px2);
    const float* wb = wgt + (long)b * wgt_bs;
    #pragma unroll
    for (int i = 0; i < 16; i++) {
        int li = tid + i * 256;
        int ic = li >> 6, l2 = li & 63;
        ((ulonglong2*)xs)[ic * 64 + l2] = inb2[(long)ic * 16384 + l2];
    }
    #pragma unroll
    for (int i = 0; i < 16; i++) {
        int li = tid + i * 256;
        int ic = li & 63, r = li >> 6;
        float w = wb[r * 64 + ic];
        u64 p = pk2(w, w);
        int ocg = r >> 2, t = r & 3;
        if (t < 2) wsA[ic * 32 + ocg * 2 + t]     = p;
        else       wsB[ic * 32 + ocg * 2 + t - 2] = p;
    }
    __syncthreads();

    const int pxg = tid >> 4;
    const int ocg = tid & 15;
    u64 acc[4][8];
    #pragma unroll
    for (int i = 0; i < 4; i++)
        #pragma unroll
        for (int j = 0; j < 8; j++) acc[i][j] = 0ULL;

    const u64* xrow = xs + pxg * 8;
    const u64* wa = wsA + ocg * 2;
    const u64* wb2 = wsB + ocg * 2;

    #pragma unroll 4
    for (int ic = 0; ic < 64; ic++) {
        ulonglong2 x01 = *(const ulonglong2*)(xrow + ic * 128);
        ulonglong2 x23 = *(const ulonglong2*)(xrow + ic * 128 + 2);
        ulonglong2 x45 = *(const ulonglong2*)(xrow + ic * 128 + 4);
        ulonglong2 x67 = *(const ulonglong2*)(xrow + ic * 128 + 6);
        ulonglong2 wA  = *(const ulonglong2*)(wa + ic * 32);
        ulonglong2 wB  = *(const ulonglong2*)(wb2 + ic * 32);
        u64 w4[4] = { wA.x, wA.y, wB.x, wB.y };
        u64 x8[8] = { x01.x, x01.y, x23.x, x23.y, x45.x, x45.y, x67.x, x67.y };
        #pragma unroll
        for (int i = 0; i < 4; i++)
            #pragma unroll
            for (int j = 0; j < 8; j++) acc[i][j] = fma2(w4[i], x8[j], acc[i][j]);
    }

    u64* ob = out2 + (long)b * out_bs2 + (long)(ocg * 4) * NPAIR + px2 + pxg * 8;
    #pragma unroll
    for (int i = 0; i < 4; i++) {
        ulonglong2* dst = (ulonglong2*)(ob + (long)i * NPAIR);
        dst[0] = make_ulonglong2(acc[i][0], acc[i][1]);
        dst[1] = make_ulonglong2(acc[i][2], acc[i][3]);
        dst[2] = make_ulonglong2(acc[i][4], acc[i][5]);
        dst[3] = make_ulonglong2(acc[i][6], acc[i][7]);
    }
}

// ---------------- K2: depthwise 3x3 pad 1 + fused sumsq partials ----------------
__global__ __launch_bounds__(256) void dw_kernel(const float* __restrict__ w_dw)
{
    __shared__ float s[10][258];
    __shared__ float sm8[8];
    const int b = blockIdx.z, ch = blockIdx.y, y0 = blockIdx.x * 8;
    const float* in  = g_qkv  + ((long)b * 192 + ch) * NPIX;
    float*       out = g_qkvd + ((long)b * 192 + ch) * NPIX;
    const int tid = threadIdx.x;

    #pragma unroll
    for (int r = 0; r < 10; r++) {
        int y = y0 - 1 + r;
        s[r][tid + 1] = (y >= 0 && y < 256) ? in[y * 256 + tid] : 0.f;
    }
    if (tid < 10) { s[tid][0] = 0.f; s[tid][257] = 0.f; }
    float w[9];
    #pragma unroll
    for (int i = 0; i < 9; i++) w[i] = w_dw[ch * 9 + i];
    __syncthreads();

    float ss = 0.f;
    #pragma unroll
    for (int ry = 0; ry < 8; ry++) {
        float a = 0.f;
        #pragma unroll
        for (int dy = 0; dy < 3; dy++)
            #pragma unroll
            for (int dx = 0; dx < 3; dx++)
                a += w[dy * 3 + dx] * s[ry + dy][tid + dx];
        out[(y0 + ry) * 256 + tid] = a;
        ss += a * a;
    }
    #pragma unroll
    for (int o = 16; o; o >>= 1) ss += __shfl_xor_sync(0xffffffffu, ss, o);
    if ((tid & 31) == 0) sm8[tid >> 5] = ss;
    __syncthreads();
    if (tid == 0 && ch < 128) {
        float t = 0.f;
        #pragma unroll
        for (int i = 0; i < 8; i++) t += sm8[i];
        g_sspart[((long)b * 128 + ch) * 32 + blockIdx.x] = t;
    }
}

// ---------------- K4: attn partials raw[c][d] = sum_n q[c][n]k[d][n] ------------
// Each warp computes the FULL 32x32 for its own n slice (f32x2 over n-pairs).
// XOR-4 swizzle on n makes all operand LDS.128 single-phase.
#define QST 132
__global__ __launch_bounds__(256) void attn_kernel()
{
    __shared__ alignas(16) float qs[2 * 32 * QST];
    float* ks = qs + 32 * QST;
    const int cx = blockIdx.x;            // 64 chunks of 1024 n
    const int h  = blockIdx.y;
    const int b  = blockIdx.z;
    const float* qb = g_qkvd + ((long)b * 192 +      h * 32) * NPIX;
    const float* kb = g_qkvd + ((long)b * 192 + 64 + h * 32) * NPIX;
    const int tid = threadIdx.x, wid = tid >> 5, lane = tid & 31;
    const int cg = lane >> 3, dg = lane & 7;
    const int swq = cg * 4;
    const int swk = ((dg >> 1) & 3) * 4;

    u64 acc[8][4];
    #pragma unroll
    for (int i = 0; i < 8; i++)
        #pragma unroll
        for (int j = 0; j < 4; j++) acc[i][j] = 0ULL;

    for (int sc = 0; sc < 8; sc++) {
        const int n0 = cx * 1024 + sc * 128;
        if (sc) __syncthreads();
        #pragma unroll
        for (int i = 0; i < 4; i++) {
            int li = tid + i * 256;        // 0..1023
            int c = li >> 5, f4 = li & 31;
            int sw = ((c >> 3) & 3) * 4;
            float4 qv = *(const float4*)(qb + (long)c * NPIX + n0 + f4 * 4);
            float4 kv = *(const float4*)(kb + (long)c * NPIX + n0 + f4 * 4);
            *(float4*)(qs + c * QST + ((f4 * 4) ^ sw)) = qv;
            *(float4*)(ks + c * QST + ((f4 * 4) ^ sw)) = kv;
        }
        __syncthreads();
        #pragma unroll
        for (int qd = 0; qd < 4; qd++) {
            const int nn4 = wid * 16 + qd * 4;
            ulonglong2 q4[8], k4[4];
            #pragma unroll
            for (int i = 0; i < 8; i++)
                q4[i] = *(const ulonglong2*)(qs + (cg * 8 + i) * QST + (nn4 ^ swq));
            #pragma unroll
            for (int j = 0; j < 4; j++)
                k4[j] = *(const ulonglong2*)(ks + (dg * 4 + j) * QST + (nn4 ^ swk));
            #pragma unroll
            for (int i = 0; i < 8; i++)
                #pragma unroll
                for (int j = 0; j < 4; j++) {
                    acc[i][j] = fma2(q4[i].x, k4[j].x, acc[i][j]);
                    acc[i][j] = fma2(q4[i].y, k4[j].y, acc[i][j]);
                }
        }
    }

    __syncthreads();
    float* red = qs;   // 8 warps x 32*33 = 8448 floats = 2*32*QST
    #pragma unroll
    for (int i = 0; i < 8; i++)
        #pragma unroll
        for (int j = 0; j < 4; j++) {
            int c = cg * 8 + i, d = dg * 4 + j;
            red[wid * 1056 + c * 33 + d] = lo32(acc[i][j]) + hi32(acc[i][j]);
        }
    __syncthreads();

    const int c0 = (tid * 4) >> 5, d0 = (tid * 4) & 31;
    float o0 = 0.f, o1 = 0.f, o2 = 0.f, o3 = 0.f;
    #pragma unroll
    for (int w = 0; w < 8; w++) {
        const float* rp = red + w * 1056 + c0 * 33 + d0;
        o0 += rp[0]; o1 += rp[1]; o2 += rp[2]; o3 += rp[3];
    }
    float* gp = g_part + (((long)b * 2 + h) * 64 + cx) * 1024 + tid * 4;
    gp[0] = o0; gp[1] = o1; gp[2] = o2; gp[3] = o3;
}

// ---------------- K5: norms + topk-masked softmax x3 + combine + fused P --------
__global__ __launch_bounds__(1024) void soft_kernel(
    const float* __restrict__ temp, const float* __restrict__ a1,
    const float* __restrict__ a2, const float* __restrict__ a3,
    const float* __restrict__ wp)
{
    const int h = blockIdx.x, b = blockIdx.y;
    __shared__ float invq[32], invk[32];
    __shared__ float M[32 * 33];
    const int tid = threadIdx.x;

    if (tid < 64) {
        int isk = tid >> 5, cc = tid & 31;
        const float* sp = g_sspart + ((long)b * 128 + isk * 64 + h * 32 + cc) * 32;
        float s = 0.f;
        #pragma unroll
        for (int p = 0; p < 32; p++) s += sp[p];
        float iv = 1.f / fmaxf(sqrtf(s), 1e-12f);
        if (isk) invk[cc] = iv; else invq[cc] = iv;
    }
    __syncthreads();

    const int c = tid >> 5, d = tid & 31;
    const float* pp = g_part + (((long)b * 2 + h) * 64) * 1024 + c * 32 + d;
    float raw = 0.f;
    #pragma unroll 16
    for (int p = 0; p < 64; p++) raw += pp[p * 1024];

    float v = raw * invq[c] * invk[d] * temp[h];

    // rank with torch.topk tie-break (earlier index wins)
    int rank = 0;
    #pragma unroll
    for (int j = 0; j < 32; j++) {
        float vj = __shfl_sync(0xffffffffu, v, j);
        rank += (vj > v) || (vj == v && j < d);
    }
    float m = v;
    #pragma unroll
    for (int o = 16; o; o >>= 1) m = fmaxf(m, __shfl_xor_sync(0xffffffffu, m, o));
    float e  = expf(v - m);
    float e1 = rank < 16 ? e : 0.f;
    float e2 = rank < 21 ? e : 0.f;
    float e3 = rank < 24 ? e : 0.f;
    float s1 = e1, s2 = e2, s3 = e3;
    #pragma unroll
    for (int o = 16; o; o >>= 1) {
        s1 += __shfl_xor_sync(0xffffffffu, s1, o);
        s2 += __shfl_xor_sync(0xffffffffu, s2, o);
        s3 += __shfl_xor_sync(0xffffffffu, s3, o);
    }
    M[c * 33 + d] = e1 * (a1[0] / s1) + e2 * (a2[0] / s2) + e3 * (a3[0] / s3);
    __syncthreads();

    // P[b][oc][h*32+d] = sum_c wp[oc][h*32+c] * M[c][d] (fuses out-einsum + proj)
    const int oc = tid >> 5, dd = tid & 31;
    float p0 = 0.f, p1 = 0.f;
    #pragma unroll
    for (int cc = 0; cc < 32; cc++) {
        float mm = M[cc * 33 + dd];
        p0 += wp[oc * 64 + h * 32 + cc] * mm;
        p1 += wp[(oc + 32) * 64 + h * 32 + cc] * mm;
    }
    g_P[b * 4096 + oc * 64 + h * 32 + dd]        = p0;
    g_P[b * 4096 + (oc + 32) * 64 + h * 32 + dd] = p1;
}

// ---------------- launch --------------------------------------------------------
extern "C" void kernel_launch(void* const* d_in, const int* in_sizes, int n_in,
                              void* d_out, int out_size)
{
    const float* x      = (const float*)d_in[0];
    const float* w_qkv  = (const float*)d_in[1];
    const float* w_dw   = (const float*)d_in[2];
    const float* w_proj = (const float*)d_in[3];
    const float* temp   = (const float*)d_in[4];
    const float* a1     = (const float*)d_in[5];
    const float* a2     = (const float*)d_in[6];
    const float* a3     = (const float*)d_in[7];

    cudaFuncSetAttribute(qkv_kernel,
                         cudaFuncAttributeMaxDynamicSharedMemorySize, 114688);
    cudaFuncSetAttribute(pw_gemm_kernel,
                         cudaFuncAttributeMaxDynamicSharedMemorySize, 98304);

    void *pqkv, *pqkvd, *pP;
    cudaGetSymbolAddress(&pqkv,  g_qkv);
    cudaGetSymbolAddress(&pqkvd, g_qkvd);
    cudaGetSymbolAddress(&pP,    g_P);

    // K1: qkv 1x1 conv, all batches, all 192 oc per block
    qkv_kernel<<<dim3(256, 1, 8), 256, 114688>>>(
        (const u64*)x, w_qkv, (u64*)pqkv);
    // K2: depthwise 3x3 (+ fused q/k sumsq partials)
    dw_kernel<<<dim3(32, 192, 8), 256>>>(w_dw);
    // K4: attn raw dot-product partials
    attn_kernel<<<dim3(64, 2, 8), 256>>>();
    // K5: norms + topk softmax x3 + combine + fused P
    soft_kernel<<<dim3(2, 8), 1024>>>(temp, a1, a2, a3, w_proj);
    // K6: final = P @ V (V = g_qkvd channels 128..191) -> d_out
    pw_gemm_kernel<<<dim3(256, 1, 8), 256, 98304>>>(
        (const u64*)pqkvd + 128L * NPAIR, (const float*)pP, (u64*)d_out,
        192L * NPAIR, 64L * NPAIR, 4096);
}